// round 15
// baseline (speedup 1.0000x reference)
#include <cuda_runtime.h>
#include <cuda_bf16.h>
#include <math.h>
#include <stdint.h>

#define LQ 2048
#define DM 1024
#define NG 4
#define NH 4
#define HD 64
#define GC 256
#define SCALE 0.125f
#define LN_EPS 1e-5f

#define K_PROJ 1024
#define K_S    256
#define K_AV   8192
#define PAD 40                  // smem row stride (bf16) — conflict-free ldmatrix
#define NSTAGE 3
#define TILE_ELEMS (128 * PAD)                  // 5120 bf16 per tile buffer
#define SMEM_BYTES (NSTAGE * TILE_ELEMS * 2 * 2) // 61440 B dynamic smem

// ---------------- scratch ----------------
__device__ __align__(256) __nv_bfloat16 g_xb [LQ * DM];
__device__ __align__(256) __nv_bfloat16 g_Wqb[DM * DM];
__device__ __align__(256) __nv_bfloat16 g_Wkvb[2 * DM * DM];
__device__ __align__(256) __nv_bfloat16 g_Wob[DM * DM];
__device__ __align__(256) __nv_bfloat16 g_Qb [NG * LQ * GC];     // [g][l][256]
__device__ __align__(256) __nv_bfloat16 g_Kb [NG * LQ * GC];     // [G][l][256]
__device__ __align__(256) __nv_bfloat16 g_Vb [NG * LQ * GC];     // [G][k][256]
__device__ __align__(256) __nv_bfloat16 g_Vtb[GC * NG * LQ];     // [c][G*2048+k]
__device__ __align__(256) __nv_bfloat16 g_Sb[(size_t)NG * LQ * NG * LQ]; // bf16 scores
__device__ __align__(256) __nv_bfloat16 g_Pb[(size_t)NG * LQ * NG * LQ]; // bf16 probs
__device__ __align__(256) float g_O[LQ * DM];
__device__ __align__(256) __nv_bfloat16 g_Ob[LQ * DM];
__device__ __align__(256) float g_P[LQ * DM];

// ---------------- helpers ----------------
__device__ __forceinline__ unsigned smem_u32(const void* p) {
    return (unsigned)__cvta_generic_to_shared(p);
}
__device__ __forceinline__ uint32_t pack_bf162(float a, float b) {
    __nv_bfloat162 h = __floats2bfloat162_rn(a, b);
    return *reinterpret_cast<uint32_t*>(&h);
}
#define CP_ASYNC16(dst, src) \
    asm volatile("cp.async.cg.shared.global [%0], [%1], 16;" :: "r"(dst), "l"(src))
#define CP_COMMIT() asm volatile("cp.async.commit_group;")
#define CP_WAIT(n)  asm volatile("cp.async.wait_group %0;" :: "n"(n))

__device__ __forceinline__ void ldmx4(uint32_t* r, unsigned addr) {
    asm volatile("ldmatrix.sync.aligned.m8n8.x4.shared.b16 {%0,%1,%2,%3}, [%4];"
                 : "=r"(r[0]), "=r"(r[1]), "=r"(r[2]), "=r"(r[3]) : "r"(addr));
}
__device__ __forceinline__ void mma16816(float* c, const uint32_t* a, const uint32_t* b) {
    asm volatile("mma.sync.aligned.m16n8k16.row.col.f32.bf16.bf16.f32 "
                 "{%0,%1,%2,%3}, {%4,%5,%6,%7}, {%8,%9}, {%0,%1,%2,%3};"
                 : "+f"(c[0]), "+f"(c[1]), "+f"(c[2]), "+f"(c[3])
                 : "r"(a[0]), "r"(a[1]), "r"(a[2]), "r"(a[3]), "r"(b[0]), "r"(b[1]));
}

// ---------------- bf16 MMA GEMM core: 128x128 tile of alpha * A @ B^T ----------------
// A [M][K], B [N][K] bf16 row-major; 128 threads (4 warps, 2x2, 64x64 warp tile);
// 3-stage cp.async pipeline in 60KB DYNAMIC smem; BK=32. Epilogue epi(m, c, v0, v1).
template <typename Epi>
__device__ __forceinline__ void mma_gemm_core(
    const __nv_bfloat16* __restrict__ A, int lda,
    const __nv_bfloat16* __restrict__ B, int ldb,
    int K, float alpha, Epi epi)
{
    extern __shared__ __align__(16) __nv_bfloat16 dynsm[];
    // A tiles: dynsm[0 .. NSTAGE*TILE_ELEMS); B tiles follow.
    const unsigned asb = smem_u32(dynsm);
    const unsigned bsb = asb + NSTAGE * TILE_ELEMS * 2;

    const int t = threadIdx.x;
    const int lane = t & 31, w = t >> 5;
    const int wm = w & 1, wn = w >> 1;          // 2 warps along M, 2 along N
    const int m0 = blockIdx.y * 128, n0 = blockIdx.x * 128;

    float acc[4][8][4];
#pragma unroll
    for (int i = 0; i < 4; i++)
#pragma unroll
        for (int j = 0; j < 8; j++)
#pragma unroll
            for (int q = 0; q < 4; q++) acc[i][j][q] = 0.f;

    auto load_chunk = [&](int k0, int buf) {
#pragma unroll
        for (int h = 0; h < 4; h++) {
            int s = t + h * 128;                // 512 16B segments per tile
            int row = s >> 2, seg = s & 3;
            unsigned off = (unsigned)(buf * TILE_ELEMS + row * PAD + seg * 8) * 2;
            CP_ASYNC16(asb + off, A + (size_t)(m0 + row) * lda + k0 + seg * 8);
            CP_ASYNC16(bsb + off, B + (size_t)(n0 + row) * ldb + k0 + seg * 8);
        }
    };

    const int nch = K >> 5;                     // BK = 32
    load_chunk(0, 0);  CP_COMMIT();
    load_chunk(32, 1); CP_COMMIT();

    for (int ch = 0; ch < nch; ch++) {
        int buf = ch % NSTAGE;
        CP_WAIT(1);                             // chunk ch resident
        __syncthreads();                        // all warps done with buf we're about to refill
        if (ch + 2 < nch) {
            load_chunk((ch + 2) << 5, (ch + 2) % NSTAGE);
            CP_COMMIT();
        }

#pragma unroll
        for (int kk = 0; kk < 32; kk += 16) {
            uint32_t af[4][4];
#pragma unroll
            for (int i = 0; i < 4; i++) {
                unsigned ad = asb + (unsigned)(buf * TILE_ELEMS +
                              (wm * 64 + i * 16 + (lane & 15)) * PAD +
                              kk + (lane >> 4) * 8) * 2;
                ldmx4(af[i], ad);
            }
            uint32_t bfr[8][2];
#pragma unroll
            for (int jj = 0; jj < 4; jj++) {
                uint32_t r[4];
                unsigned bd = bsb + (unsigned)(buf * TILE_ELEMS +
                              (wn * 64 + jj * 16 + (lane & 15)) * PAD +
                              kk + (lane >> 4) * 8) * 2;
                ldmx4(r, bd);
                bfr[2 * jj][0] = r[0]; bfr[2 * jj + 1][0] = r[1];
                bfr[2 * jj][1] = r[2]; bfr[2 * jj + 1][1] = r[3];
            }
#pragma unroll
            for (int i = 0; i < 4; i++)
#pragma unroll
                for (int j = 0; j < 8; j++)
                    mma16816(acc[i][j], af[i], bfr[j]);
        }
        __syncthreads();                        // compute done before next refill of this buf
    }

    const int cr = lane >> 2, cc = (lane & 3) * 2;
#pragma unroll
    for (int i = 0; i < 4; i++)
#pragma unroll
        for (int j = 0; j < 8; j++) {
            int rr = m0 + wm * 64 + i * 16 + cr;
            int c  = n0 + wn * 64 + j * 8 + cc;
            epi(rr, c, alpha * acc[i][j][0], alpha * acc[i][j][1]);
            epi(rr + 8, c, alpha * acc[i][j][2], alpha * acc[i][j][3]);
        }
}

// ---------------- GEMM wrapper kernels (128 threads, dynamic smem) ----------------
__global__ void __launch_bounds__(128) k_mma_q(void) {
    auto epi = [](int m, int c, float a, float b) {
        int g = c >> 8, cc = c & 255;
        *(uint32_t*)&g_Qb[((size_t)g * LQ + m) * GC + cc] = pack_bf162(a, b);
    };
    mma_gemm_core(g_xb, DM, g_Wqb, DM, K_PROJ, 1.0f, epi);
}
__global__ void __launch_bounds__(128) k_mma_kv(void) {
    auto epi = [](int m, int c, float a, float b) {
        int Gh = c >> 7, G = Gh >> 2, h = Gh & 3, cc = c & 127;
        __nv_bfloat16* dst = (cc < 64) ? g_Kb : g_Vb;
        *(uint32_t*)&dst[((size_t)G * LQ + m) * GC + h * 64 + (cc & 63)] = pack_bf162(a, b);
    };
    mma_gemm_core(g_xb, DM, g_Wkvb, DM, K_PROJ, 1.0f, epi);
}
__global__ void __launch_bounds__(128) k_mma_s(void) {
    int g = blockIdx.z >> 2, G = blockIdx.z & 3;
    const __nv_bfloat16* A = g_Qb + (size_t)g * LQ * GC;
    const __nv_bfloat16* B = g_Kb + (size_t)G * LQ * GC;
    __nv_bfloat16* Cb = g_Sb + (size_t)g * LQ * (NG * LQ) + G * LQ;
    auto epi = [Cb](int m, int c, float a, float b) {
        *(uint32_t*)&Cb[(size_t)m * (NG * LQ) + c] = pack_bf162(a, b);
    };
    mma_gemm_core(A, GC, B, GC, K_S, SCALE, epi);
}
__global__ void __launch_bounds__(128) k_mma_av(void) {
    int g = blockIdx.z >> 1, ks = blockIdx.z & 1;
    const __nv_bfloat16* A = g_Pb + (size_t)g * LQ * (NG * LQ) + ks * (K_AV / 2);
    const __nv_bfloat16* B = g_Vtb + ks * (K_AV / 2);
    float* C = g_O + g * GC;
    auto epi = [C](int m, int c, float a, float b) {
        atomicAdd(&C[(size_t)m * DM + c], a);
        atomicAdd(&C[(size_t)m * DM + c + 1], b);
    };
    mma_gemm_core(A, NG * LQ, B, NG * LQ, K_AV / 2, 1.0f, epi);
}
__global__ void __launch_bounds__(128) k_mma_o(void) {
    auto epi = [](int m, int c, float a, float b) {
        *(float2*)&g_P[(size_t)m * DM + c] = make_float2(a, b);
    };
    mma_gemm_core(g_Ob, DM, g_Wob, DM, K_PROJ, 1.0f, epi);
}

// ---------------- fused cast kernel ----------------
__device__ __forceinline__ uint4 cast8(const float* v) {
    __nv_bfloat16 h[8];
#pragma unroll
    for (int i = 0; i < 8; i++) h[i] = __float2bfloat16(v[i]);
    return *reinterpret_cast<uint4*>(h);
}
__device__ __forceinline__ void cast_range(const float* src, __nv_bfloat16* dst, int i8) {
    float v[8];
    *(float4*)v = *(const float4*)(src + i8);
    *(float4*)(v + 4) = *(const float4*)(src + i8 + 4);
    *(uint4*)(dst + i8) = cast8(v);
}
__global__ void k_cast_all(const float* __restrict__ x, const float* __restrict__ Wq,
                           const float* __restrict__ Wkv, const float* __restrict__ Wo) {
    int u = blockIdx.x * blockDim.x + threadIdx.x;     // 0 .. 768K-1
    if (u < 262144)           cast_range(x,   g_xb,   u * 8);
    else if (u < 393216)      cast_range(Wq,  g_Wqb,  (u - 262144) * 8);
    else if (u < 655360)      cast_range(Wkv, g_Wkvb, (u - 393216) * 8);
    else                      cast_range(Wo,  g_Wob,  (u - 655360) * 8);
}
__global__ void k_cast_o() {
    int i8 = (blockIdx.x * blockDim.x + threadIdx.x) * 8;
    cast_range(g_O, g_Ob, i8);
}

// ---------------- V transpose (bf16): Vb[G][k][c] -> Vtb[c][G*2048+k] ----------------
__global__ void k_transpose_v() {
    __shared__ __nv_bfloat16 tile[32][33];
    int G = blockIdx.z;
    int c0 = blockIdx.x * 32;
    int k0 = blockIdx.y * 32;
#pragma unroll
    for (int r = threadIdx.y; r < 32; r += 8)
        tile[r][threadIdx.x] = g_Vb[((size_t)G * LQ + k0 + r) * GC + c0 + threadIdx.x];
    __syncthreads();
#pragma unroll
    for (int r = threadIdx.y; r < 32; r += 8)
        g_Vtb[(size_t)(c0 + r) * (NG * LQ) + G * LQ + k0 + threadIdx.x] =
            tile[threadIdx.x][r];
}

// ---------------- softmax: bf16 scores -> bf16 probs ----------------
__global__ void k_softmax_b() {
    __shared__ float smx[8], ssm[8];
    const int t = threadIdx.x;
    const int bx = blockIdx.x;                 // ((g*2048)+m)*4 + G
    const int G = bx & 3, m = (bx >> 2) & 2047, g = bx >> 13;
    const __nv_bfloat16* p = g_Sb + (size_t)bx * LQ;

    __nv_bfloat16 hv[8];
    *(uint4*)hv = *(const uint4*)(p + t * 8);
    float v[8];
#pragma unroll
    for (int j = 0; j < 8; j++) v[j] = __bfloat162float(hv[j]);

    float mx = -INFINITY;
#pragma unroll
    for (int j = 0; j < 8; j++) mx = fmaxf(mx, v[j]);
#pragma unroll
    for (int o = 16; o; o >>= 1) mx = fmaxf(mx, __shfl_xor_sync(~0u, mx, o));
    if ((t & 31) == 0) smx[t >> 5] = mx;
    __syncthreads();
    float bmax = smx[0];
#pragma unroll
    for (int i = 1; i < 8; i++) bmax = fmaxf(bmax, smx[i]);

    float s = 0.f;
#pragma unroll
    for (int j = 0; j < 8; j++) { v[j] = __expf(v[j] - bmax); s += v[j]; }
#pragma unroll
    for (int o = 16; o; o >>= 1) s += __shfl_xor_sync(~0u, s, o);
    if ((t & 31) == 0) ssm[t >> 5] = s;
    __syncthreads();
    float tot = 0.f;
#pragma unroll
    for (int i = 0; i < 8; i++) tot += ssm[i];
    float inv = 1.0f / tot;
#pragma unroll
    for (int j = 0; j < 8; j++) v[j] *= inv;

    *(uint4*)(g_Pb + ((size_t)g * LQ + m) * (NG * LQ) + G * LQ + t * 8) = cast8(v);
}

// ---------------- residual + LayerNorm ----------------
__global__ void k_ln(const float* __restrict__ x,
                     const float* __restrict__ gamma,
                     const float* __restrict__ beta,
                     float* __restrict__ out) {
    __shared__ float s1[8], s2[8];
    const int t = threadIdx.x;
    const size_t base = (size_t)blockIdx.x * DM;

    float v[4];
    float s = 0.f, ss = 0.f;
#pragma unroll
    for (int j = 0; j < 4; j++) {
        int c = t + 256 * j;
        float y = x[base + c] + g_P[base + c];
        v[j] = y; s += y; ss += y * y;
    }
#pragma unroll
    for (int o = 16; o; o >>= 1) { s += __shfl_xor_sync(~0u, s, o); ss += __shfl_xor_sync(~0u, ss, o); }
    if ((t & 31) == 0) { s1[t >> 5] = s; s2[t >> 5] = ss; }
    __syncthreads();
    float ts = 0.f, tss = 0.f;
#pragma unroll
    for (int i = 0; i < 8; i++) { ts += s1[i]; tss += s2[i]; }
    float mu = ts * (1.0f / DM);
    float var = tss * (1.0f / DM) - mu * mu;
    float inv = rsqrtf(var + LN_EPS);
#pragma unroll
    for (int j = 0; j < 4; j++) {
        int c = t + 256 * j;
        out[base + c] = gamma[c] * (v[j] - mu) * inv + beta[c];
    }
}

// ---------------- launch ----------------
extern "C" void kernel_launch(void* const* d_in, const int* in_sizes, int n_in,
                              void* d_out, int out_size) {
    const float* x     = (const float*)d_in[0];
    const float* Wq    = (const float*)d_in[1];
    const float* Wkv   = (const float*)d_in[2];
    const float* Wo    = (const float*)d_in[3];
    const float* gamma = (const float*)d_in[4];
    const float* beta  = (const float*)d_in[5];
    float* out = (float*)d_out;

    // opt-in to >48KB dynamic smem (idempotent host-side attribute; capture-safe)
    cudaFuncSetAttribute(k_mma_q,  cudaFuncAttributeMaxDynamicSharedMemorySize, SMEM_BYTES);
    cudaFuncSetAttribute(k_mma_kv, cudaFuncAttributeMaxDynamicSharedMemorySize, SMEM_BYTES);
    cudaFuncSetAttribute(k_mma_s,  cudaFuncAttributeMaxDynamicSharedMemorySize, SMEM_BYTES);
    cudaFuncSetAttribute(k_mma_av, cudaFuncAttributeMaxDynamicSharedMemorySize, SMEM_BYTES);
    cudaFuncSetAttribute(k_mma_o,  cudaFuncAttributeMaxDynamicSharedMemorySize, SMEM_BYTES);

    float* po;
    cudaGetSymbolAddress((void**)&po, g_O);

    k_cast_all<<<3072, 256>>>(x, Wq, Wkv, Wo);

    k_mma_q <<<dim3(DM / 128, LQ / 128), 128, SMEM_BYTES>>>();
    k_mma_kv<<<dim3(2 * DM / 128, LQ / 128), 128, SMEM_BYTES>>>();
    k_transpose_v<<<dim3(GC / 32, LQ / 32, NG), dim3(32, 8)>>>();

    k_mma_s   <<<dim3(LQ / 128, LQ / 128, NG * NG), 128, SMEM_BYTES>>>();
    k_softmax_b<<<NG * LQ * NG, 256>>>();
    cudaMemsetAsync(po, 0, (size_t)LQ * DM * sizeof(float));
    k_mma_av  <<<dim3(GC / 128, LQ / 128, NG * 2), 128, SMEM_BYTES>>>();

    k_cast_o<<<(LQ * DM) / 2048, 256>>>();
    k_mma_o<<<dim3(DM / 128, LQ / 128), 128, SMEM_BYTES>>>();
    k_ln<<<LQ, 256>>>(x, gamma, beta, out);
}